// round 5
// baseline (speedup 1.0000x reference)
#include <cuda_runtime.h>
#include <math.h>
#include <stdint.h>

// Problem dims
#define V_ 32000
#define E_ 1024
#define H_ 1024
#define A_ 10
#define S_ 512
#define B_ 64

#define NSPLIT 16

// Scratch layout (floats)
#define OFF_HWA1 0             // 640
#define OFF_E    1024          // S*B = 32768
#define OFF_XC   33792         // B*(E+H) = 131072
#define OFF_GIP  164864        // 4*B*3H = 786432
#define OFF_GHP  951296        // 4*B*3H = 786432
#define OFF_CP   1737728       // NSPLIT*B*H = 1048576
#define SCRATCH_FLOATS 2786304

__device__ float g_scratch[SCRATCH_FLOATS];

// ---------------------------------------------------------------------------
// hWa1[b][a] = sum_h h_last[b,h] * Wa1[a,h]
// ---------------------------------------------------------------------------
__global__ __launch_bounds__(256) void k_hWa1(const float* __restrict__ h,
                                              const float* __restrict__ Wa1,
                                              float* __restrict__ hWa1)
{
    const int b = blockIdx.x;
    const int tid = threadIdx.x;
    float4 hv = ((const float4*)(h + (size_t)b * H_))[tid];
    float p[A_];
#pragma unroll
    for (int a = 0; a < A_; a++) {
        float4 w = ((const float4*)(Wa1 + (size_t)a * (2 * H_)))[tid];
        p[a] = hv.x * w.x + hv.y * w.y + hv.z * w.z + hv.w * w.w;
    }
    __shared__ float red[8][A_];
    const int lane = tid & 31, wid = tid >> 5;
#pragma unroll
    for (int a = 0; a < A_; a++) {
        float v = p[a];
        v += __shfl_xor_sync(0xffffffffu, v, 16);
        v += __shfl_xor_sync(0xffffffffu, v, 8);
        v += __shfl_xor_sync(0xffffffffu, v, 4);
        v += __shfl_xor_sync(0xffffffffu, v, 2);
        v += __shfl_xor_sync(0xffffffffu, v, 1);
        if (lane == 0) red[wid][a] = v;
    }
    __syncthreads();
    if (tid < A_) {
        float s = 0.f;
#pragma unroll
        for (int w = 0; w < 8; w++) s += red[w][tid];
        hWa1[b * A_ + tid] = s;
    }
}

// ---------------------------------------------------------------------------
// scores: e[r] = sum_a Wa2[a]*tanh(hWa1[b][a] + enc[r,:].Wa1[a,H:])
// ---------------------------------------------------------------------------
__global__ __launch_bounds__(256) void k_scores(const float* __restrict__ enc,
                                                const float* __restrict__ Wa1,
                                                const float* __restrict__ Wa2,
                                                const float* __restrict__ hWa1,
                                                float* __restrict__ e_out)
{
    __shared__ float Wsh[A_ * H_];   // 40KB
    const int tid = threadIdx.x;
    for (int id = tid; id < A_ * (H_ / 4); id += 256) {
        int a = id >> 8;
        int c4 = id & 255;
        ((float4*)Wsh)[a * 256 + c4] =
            *(const float4*)(Wa1 + (size_t)a * (2 * H_) + H_ + (c4 << 2));
    }
    __syncthreads();

    const int lane = tid & 31, wid = tid >> 5;
    const size_t r0 = (size_t)blockIdx.x * 32 + wid * 4;
    const float4* e4 = (const float4*)enc;

    float acc0[A_], acc1[A_], acc2[A_], acc3[A_];
#pragma unroll
    for (int a = 0; a < A_; a++) { acc0[a] = 0.f; acc1[a] = 0.f; acc2[a] = 0.f; acc3[a] = 0.f; }

#pragma unroll
    for (int it = 0; it < 8; it++) {
        const int h4 = it * 32 + lane;
        float4 x0 = e4[(r0 + 0) * 256 + h4];
        float4 x1 = e4[(r0 + 1) * 256 + h4];
        float4 x2 = e4[(r0 + 2) * 256 + h4];
        float4 x3 = e4[(r0 + 3) * 256 + h4];
#pragma unroll
        for (int a = 0; a < A_; a++) {
            float4 w = ((const float4*)Wsh)[a * 256 + h4];
            acc0[a] += x0.x * w.x + x0.y * w.y + x0.z * w.z + x0.w * w.w;
            acc1[a] += x1.x * w.x + x1.y * w.y + x1.z * w.z + x1.w * w.w;
            acc2[a] += x2.x * w.x + x2.y * w.y + x2.z * w.z + x2.w * w.w;
            acc3[a] += x3.x * w.x + x3.y * w.y + x3.z * w.z + x3.w * w.w;
        }
    }
#pragma unroll
    for (int a = 0; a < A_; a++) {
        float v;
        v = acc0[a];
        v += __shfl_xor_sync(0xffffffffu, v, 16); v += __shfl_xor_sync(0xffffffffu, v, 8);
        v += __shfl_xor_sync(0xffffffffu, v, 4);  v += __shfl_xor_sync(0xffffffffu, v, 2);
        v += __shfl_xor_sync(0xffffffffu, v, 1);  acc0[a] = v;
        v = acc1[a];
        v += __shfl_xor_sync(0xffffffffu, v, 16); v += __shfl_xor_sync(0xffffffffu, v, 8);
        v += __shfl_xor_sync(0xffffffffu, v, 4);  v += __shfl_xor_sync(0xffffffffu, v, 2);
        v += __shfl_xor_sync(0xffffffffu, v, 1);  acc1[a] = v;
        v = acc2[a];
        v += __shfl_xor_sync(0xffffffffu, v, 16); v += __shfl_xor_sync(0xffffffffu, v, 8);
        v += __shfl_xor_sync(0xffffffffu, v, 4);  v += __shfl_xor_sync(0xffffffffu, v, 2);
        v += __shfl_xor_sync(0xffffffffu, v, 1);  acc2[a] = v;
        v = acc3[a];
        v += __shfl_xor_sync(0xffffffffu, v, 16); v += __shfl_xor_sync(0xffffffffu, v, 8);
        v += __shfl_xor_sync(0xffffffffu, v, 4);  v += __shfl_xor_sync(0xffffffffu, v, 2);
        v += __shfl_xor_sync(0xffffffffu, v, 1);  acc3[a] = v;
    }
    float tsum[A_];
#pragma unroll
    for (int a = 0; a < A_; a++) {
        float t = acc0[a];
        if (lane == 1) t = acc1[a];
        if (lane == 2) t = acc2[a];
        if (lane == 3) t = acc3[a];
        tsum[a] = t;
    }
    if (lane < 4) {
        const size_t r = r0 + lane;
        const int b = (int)(r & (B_ - 1));
        float ev = 0.f;
#pragma unroll
        for (int a = 0; a < A_; a++)
            ev += Wa2[a] * tanhf(hWa1[b * A_ + a] + tsum[a]);
        e_out[r] = ev;
    }
}

// ---------------------------------------------------------------------------
// softmax over s (axis 0) per b, in place
// ---------------------------------------------------------------------------
__global__ __launch_bounds__(256) void k_softmax(float* __restrict__ e)
{
    const int b = blockIdx.x, tid = threadIdx.x;
    __shared__ float red[256];
    float v0 = e[(size_t)tid * B_ + b];
    float v1 = e[(size_t)(tid + 256) * B_ + b];
    red[tid] = fmaxf(v0, v1);
    __syncthreads();
    for (int s = 128; s > 0; s >>= 1) {
        if (tid < s) red[tid] = fmaxf(red[tid], red[tid + s]);
        __syncthreads();
    }
    const float M = red[0];
    __syncthreads();
    float e0 = expf(v0 - M), e1 = expf(v1 - M);
    red[tid] = e0 + e1;
    __syncthreads();
    for (int s = 128; s > 0; s >>= 1) {
        if (tid < s) red[tid] += red[tid + s];
        __syncthreads();
    }
    const float inv = 1.f / red[0];
    e[(size_t)tid * B_ + b] = e0 * inv;
    e[(size_t)(tid + 256) * B_ + b] = e1 * inv;
}

// ---------------------------------------------------------------------------
// context partials: cp[sp][b][h] = sum_{s in split sp} alpha[s,b]*enc[s,b,h]
// ---------------------------------------------------------------------------
__global__ __launch_bounds__(128) void k_context_part(const float* __restrict__ alpha,
                                                      const float* __restrict__ enc,
                                                      float* __restrict__ cp)
{
    const int b = blockIdx.y;
    const int sp = blockIdx.z;
    const int h0 = blockIdx.x * 512 + threadIdx.x * 4;
    __shared__ float al[S_ / NSPLIT];
    if (threadIdx.x < S_ / NSPLIT)
        al[threadIdx.x] = alpha[(size_t)(sp * (S_ / NSPLIT) + threadIdx.x) * B_ + b];
    __syncthreads();
    float4 acc = make_float4(0.f, 0.f, 0.f, 0.f);
    const float* base = enc + (size_t)(sp * (S_ / NSPLIT)) * B_ * H_ + (size_t)b * H_ + h0;
#pragma unroll
    for (int s = 0; s < S_ / NSPLIT; s++) {
        float4 v = *(const float4*)(base + (size_t)s * (B_ * H_));
        float a = al[s];
        acc.x += a * v.x; acc.y += a * v.y; acc.z += a * v.z; acc.w += a * v.w;
    }
    *(float4*)(cp + ((size_t)sp * B_ + b) * H_ + h0) = acc;
}

// ---------------------------------------------------------------------------
// ctx reduce + xc build: xc[b] = [ emb[tok[b]] ; sum_sp cp[sp][b] ]
// grid(B), block(256)
// ---------------------------------------------------------------------------
__global__ __launch_bounds__(256) void k_ctx_xc(const int* __restrict__ tok,
                                                const float* __restrict__ emb,
                                                const float* __restrict__ cp,
                                                float* __restrict__ xc)
{
    const int b = blockIdx.x, t = threadIdx.x;
    const int tk = tok[b];
    float4* x4 = (float4*)(xc + (size_t)b * (E_ + H_));
    x4[t] = ((const float4*)(emb + (size_t)tk * E_))[t];
    float4 acc = make_float4(0.f, 0.f, 0.f, 0.f);
#pragma unroll
    for (int sp = 0; sp < NSPLIT; sp++) {
        float4 v = ((const float4*)(cp + ((size_t)sp * B_ + b) * H_))[t];
        acc.x += v.x; acc.y += v.y; acc.z += v.z; acc.w += v.w;
    }
    x4[256 + t] = acc;
}

// ---------------------------------------------------------------------------
// fp32x2 GEMM (gi & gh in one launch): z=0 -> gh, z=1 -> gi. K-split 4.
// block(128): 16(tx) x 8(ty), each 8b x 4n tile.
// ---------------------------------------------------------------------------
__global__ __launch_bounds__(128) void k_gru_gemms(const float* __restrict__ Ah_,
                                                   const float* __restrict__ Ai_,
                                                   const float* __restrict__ Whh,
                                                   const float* __restrict__ Wih,
                                                   float* __restrict__ ghp,
                                                   float* __restrict__ gip)
{
    const float* A;
    const float* W;
    float* C;
    int K, klen;
    if (blockIdx.z == 0) { A = Ah_; W = Whh; C = ghp; K = H_;      klen = 256; }
    else                 { A = Ai_; W = Wih; C = gip; K = E_ + H_; klen = 512; }

    __shared__ float As[32 * 68];
    __shared__ float Ws[32 * 66];
    const int tid = threadIdx.x;
    const int tx = tid & 15;
    const int ty = tid >> 4;
    const int n0 = blockIdx.x * 64;
    const int kbase = blockIdx.y * klen;
    const int aoff = ty * 8 + ((ty >= 4) ? 2 : 0);
    const int woff = tx * 4 + ((tx >= 8) ? 1 : 0);

    unsigned long long accp[4][4];
#pragma unroll
    for (int ip = 0; ip < 4; ip++)
#pragma unroll
        for (int j = 0; j < 4; j++) accp[ip][j] = 0ull;

    for (int kc = 0; kc < klen; kc += 32) {
        __syncthreads();
#pragma unroll
        for (int p = 0; p < 4; p++) {
            const int id = tid + p * 128;
            const int row = id >> 3;
            const int c4 = (id & 7) << 2;
            const int roffA = row + ((row >> 5) << 1);
            const int roffW = row + (row >> 5);
            float4 av = *(const float4*)(A + (size_t)row * K + kbase + kc + c4);
            As[(c4 + 0) * 68 + roffA] = av.x;
            As[(c4 + 1) * 68 + roffA] = av.y;
            As[(c4 + 2) * 68 + roffA] = av.z;
            As[(c4 + 3) * 68 + roffA] = av.w;
            float4 wv = *(const float4*)(W + (size_t)(n0 + row) * K + kbase + kc + c4);
            Ws[(c4 + 0) * 66 + roffW] = wv.x;
            Ws[(c4 + 1) * 66 + roffW] = wv.y;
            Ws[(c4 + 2) * 66 + roffW] = wv.z;
            Ws[(c4 + 3) * 66 + roffW] = wv.w;
        }
        __syncthreads();
#pragma unroll 4
        for (int kk = 0; kk < 32; kk++) {
            const float* wrow = &Ws[kk * 66 + woff];
            unsigned long long wp[4];
#pragma unroll
            for (int j = 0; j < 4; j++) {
                float w = wrow[j];
                asm("mov.b64 %0, {%1, %1};" : "=l"(wp[j]) : "f"(w));
            }
            const float* arow = &As[kk * 68 + aoff];
            unsigned long long ap[4];
#pragma unroll
            for (int ip = 0; ip < 4; ip++)
                ap[ip] = *(const unsigned long long*)(arow + 2 * ip);
#pragma unroll
            for (int ip = 0; ip < 4; ip++)
#pragma unroll
                for (int j = 0; j < 4; j++)
                    asm("fma.rn.f32x2 %0, %1, %2, %0;"
                        : "+l"(accp[ip][j]) : "l"(ap[ip]), "l"(wp[j]));
        }
    }
#pragma unroll
    for (int ip = 0; ip < 4; ip++) {
        float lo[4], hi[4];
#pragma unroll
        for (int j = 0; j < 4; j++)
            asm("mov.b64 {%0, %1}, %2;" : "=f"(lo[j]), "=f"(hi[j]) : "l"(accp[ip][j]));
        const size_t row0 = (size_t)(blockIdx.y * 64 + ty * 8 + 2 * ip);
        *(float4*)(C + row0 * (3 * H_) + n0 + tx * 4) =
            make_float4(lo[0], lo[1], lo[2], lo[3]);
        *(float4*)(C + (row0 + 1) * (3 * H_) + n0 + tx * 4) =
            make_float4(hi[0], hi[1], hi[2], hi[3]);
    }
}

// ---------------------------------------------------------------------------
// gates: merge K-split partials (4 each), GRU nonlinearity, write h_new
// ---------------------------------------------------------------------------
__global__ __launch_bounds__(256) void k_gates(const float* __restrict__ gip,
                                               const float* __restrict__ ghp,
                                               const float* __restrict__ b_ih,
                                               const float* __restrict__ b_hh,
                                               const float* __restrict__ h_last,
                                               float* __restrict__ h_new)
{
    const int idx = blockIdx.x * blockDim.x + threadIdx.x;
    const int b = idx >> 10;
    const int h = idx & 1023;
    float ir = 0.f, iz = 0.f, in_ = 0.f;
#pragma unroll
    for (int sp = 0; sp < 4; sp++) {
        const float* g = gip + (size_t)(sp * B_ + b) * (3 * H_);
        ir += g[h];
        iz += g[h + H_];
        in_ += g[h + 2 * H_];
    }
    float hr = 0.f, hz = 0.f, hn = 0.f;
#pragma unroll
    for (int sp = 0; sp < 4; sp++) {
        const float* g = ghp + (size_t)(sp * B_ + b) * (3 * H_);
        hr += g[h];
        hz += g[h + H_];
        hn += g[h + 2 * H_];
    }
    ir += b_ih[h];           hr += b_hh[h];
    iz += b_ih[h + H_];      hz += b_hh[h + H_];
    in_ += b_ih[h + 2 * H_]; hn += b_hh[h + 2 * H_];
    const float r = 1.f / (1.f + expf(-(ir + hr)));
    const float z = 1.f / (1.f + expf(-(iz + hz)));
    const float n = tanhf(in_ + r * hn);
    h_new[idx] = (1.f - z) * n + z * h_last[idx];
}

// ---------------------------------------------------------------------------
// logits GEMM, packed f32x2, fma-pipe-bound.
// C[64,32000] = A[64,1024].W[32000,1024]^T + bias
// grid(125), block(256). Tile M64 x N256, k-chunk 32, double-buffered smem.
// Thread tile m8 x n8 (32 f32x2 accumulators paired along n).
// A LDS is warp-broadcast (all lanes same row); W LDS contiguous 1024B.
// ---------------------------------------------------------------------------
#define LG_SMEM ((2 * 32 * 256 + 2 * 32 * 64) * 4)   // 81920 B

__global__ __launch_bounds__(256) void k_logits_f2(const float* __restrict__ A,
                                                   const float* __restrict__ W,
                                                   const float* __restrict__ bias,
                                                   float* __restrict__ C)
{
    extern __shared__ float sm[];
    float* Ws = sm;               // 2 bufs x 32 kk x 256 n
    float* As = sm + 16384;       // 2 bufs x 32 kk x 64 m
    const int tid = threadIdx.x;
    const int tx = tid & 31;      // n-group: 8 cols
    const int ty = tid >> 5;      // m-group (warp): 8 rows
    const int n0 = blockIdx.x * 256;

    // loader assignments
    const float* wg = W + (size_t)(n0 + tid) * 1024;   // W row = tid
    const int am = tid & 63;
    const int ak4 = tid >> 6;                          // 0..3
    const float* ag = A + (size_t)am * 1024;

    float4 wreg[8];
    float4 areg[2];
#pragma unroll
    for (int q = 0; q < 8; q++) wreg[q] = *(const float4*)(wg + q * 4);
    areg[0] = *(const float4*)(ag + ak4 * 4);
    areg[1] = *(const float4*)(ag + (ak4 + 4) * 4);

    unsigned long long acc[8][4];
#pragma unroll
    for (int m = 0; m < 8; m++)
#pragma unroll
        for (int j = 0; j < 4; j++) acc[m][j] = 0ull;

    for (int ch = 0; ch < 32; ch++) {
        float* WB = Ws + (ch & 1) * 8192;
        float* AB = As + (ch & 1) * 2048;
        // STS current regs (W: conflict-free consecutive-tid; A: consecutive am)
#pragma unroll
        for (int q = 0; q < 8; q++) {
            WB[(q * 4 + 0) * 256 + tid] = wreg[q].x;
            WB[(q * 4 + 1) * 256 + tid] = wreg[q].y;
            WB[(q * 4 + 2) * 256 + tid] = wreg[q].z;
            WB[(q * 4 + 3) * 256 + tid] = wreg[q].w;
        }
#pragma unroll
        for (int p = 0; p < 2; p++) {
            const int kk0 = (ak4 + p * 4) * 4;
            AB[(kk0 + 0) * 64 + am] = areg[p].x;
            AB[(kk0 + 1) * 64 + am] = areg[p].y;
            AB[(kk0 + 2) * 64 + am] = areg[p].z;
            AB[(kk0 + 3) * 64 + am] = areg[p].w;
        }
        __syncthreads();
        // prefetch next chunk (hidden under compute)
        if (ch < 31) {
            const float* wg2 = wg + (ch + 1) * 32;
#pragma unroll
            for (int q = 0; q < 8; q++) wreg[q] = *(const float4*)(wg2 + q * 4);
            areg[0] = *(const float4*)(ag + (ch + 1) * 32 + ak4 * 4);
            areg[1] = *(const float4*)(ag + (ch + 1) * 32 + (ak4 + 4) * 4);
        }
        // compute: 32 kk, fma-pipe-bound (32 FFMA2 vs 4 LDS.128 + 8 mov)
#pragma unroll 8
        for (int kk = 0; kk < 32; kk++) {
            const float* arow = &AB[kk * 64 + ty * 8];
            float4 af0 = *(const float4*)(arow);
            float4 af1 = *(const float4*)(arow + 4);
            unsigned long long ap[8];
            asm("mov.b64 %0, {%1, %1};" : "=l"(ap[0]) : "f"(af0.x));
            asm("mov.b64 %0, {%1, %1};" : "=l"(ap[1]) : "f"(af0.y));
            asm("mov.b64 %0, {%1, %1};" : "=l"(ap[2]) : "f"(af0.z));
            asm("mov.b64 %0, {%1, %1};" : "=l"(ap[3]) : "f"(af0.w));
            asm("mov.b64 %0, {%1, %1};" : "=l"(ap[4]) : "f"(af1.x));
            asm("mov.b64 %0, {%1, %1};" : "=l"(ap[5]) : "f"(af1.y));
            asm("mov.b64 %0, {%1, %1};" : "=l"(ap[6]) : "f"(af1.z));
            asm("mov.b64 %0, {%1, %1};" : "=l"(ap[7]) : "f"(af1.w));
            const unsigned long long* wrow =
                (const unsigned long long*)&WB[kk * 256 + tx * 8];
            unsigned long long wp0 = wrow[0], wp1 = wrow[1],
                               wp2 = wrow[2], wp3 = wrow[3];
#pragma unroll
            for (int m = 0; m < 8; m++) {
                asm("fma.rn.f32x2 %0, %1, %2, %0;" : "+l"(acc[m][0]) : "l"(ap[m]), "l"(wp0));
                asm("fma.rn.f32x2 %0, %1, %2, %0;" : "+l"(acc[m][1]) : "l"(ap[m]), "l"(wp1));
                asm("fma.rn.f32x2 %0, %1, %2, %0;" : "+l"(acc[m][2]) : "l"(ap[m]), "l"(wp2));
                asm("fma.rn.f32x2 %0, %1, %2, %0;" : "+l"(acc[m][3]) : "l"(ap[m]), "l"(wp3));
            }
        }
    }
    // epilogue
    const int colb = n0 + tx * 8;
    float4 bb0 = *(const float4*)(bias + colb);
    float4 bb1 = *(const float4*)(bias + colb + 4);
#pragma unroll
    for (int m = 0; m < 8; m++) {
        float lo[4], hi[4];
#pragma unroll
        for (int j = 0; j < 4; j++)
            asm("mov.b64 {%0, %1}, %2;" : "=f"(lo[j]), "=f"(hi[j]) : "l"(acc[m][j]));
        const size_t row = (size_t)(ty * 8 + m);
        *(float4*)(C + row * V_ + colb) =
            make_float4(lo[0] + bb0.x, hi[0] + bb0.y, lo[1] + bb0.z, hi[1] + bb0.w);
        *(float4*)(C + row * V_ + colb + 4) =
            make_float4(lo[2] + bb1.x, hi[2] + bb1.y, lo[3] + bb1.z, hi[3] + bb1.w);
    }
}

// ---------------------------------------------------------------------------
extern "C" void kernel_launch(void* const* d_in, const int* in_sizes, int n_in,
                              void* d_out, int out_size)
{
    (void)in_sizes; (void)n_in; (void)out_size;
    const int* dec_input = (const int*)d_in[0];
    const float* dec_hidden = (const float*)d_in[1];
    const float* enc = (const float*)d_in[2];
    const float* emb = (const float*)d_in[3];
    const float* Wa1 = (const float*)d_in[4];
    const float* Wa2 = (const float*)d_in[5];
    const float* W_ih = (const float*)d_in[6];
    const float* W_hh = (const float*)d_in[7];
    const float* b_ih = (const float*)d_in[8];
    const float* b_hh = (const float*)d_in[9];
    const float* W_out = (const float*)d_in[10];
    const float* b_out = (const float*)d_in[11];

    float* out = (float*)d_out;
    float* logits = out;
    float* h_new = out + (size_t)B_ * V_;

    float* scratch = nullptr;
    cudaGetSymbolAddress((void**)&scratch, g_scratch);
    float* hWa1 = scratch + OFF_HWA1;
    float* e = scratch + OFF_E;
    float* xc = scratch + OFF_XC;
    float* gip = scratch + OFF_GIP;
    float* ghp = scratch + OFF_GHP;
    float* cp = scratch + OFF_CP;

    // attention
    k_hWa1<<<B_, 256>>>(dec_hidden, Wa1, hWa1);
    k_scores<<<(S_ * B_) / 32, 256>>>(enc, Wa1, Wa2, hWa1, e);
    k_softmax<<<B_, 256>>>(e);
    k_context_part<<<dim3(2, B_, NSPLIT), 128>>>(e, enc, cp);
    k_ctx_xc<<<B_, 256>>>(dec_input, emb, cp, xc);

    // GRU (gh: z=0, gi: z=1), K-split 4 each
    k_gru_gemms<<<dim3(48, 4, 2), 128>>>(dec_hidden, xc, W_hh, W_ih, ghp, gip);
    k_gates<<<(B_ * H_) / 256, 256>>>(gip, ghp, b_ih, b_hh, dec_hidden, h_new);

    // logits
    cudaFuncSetAttribute(k_logits_f2, cudaFuncAttributeMaxDynamicSharedMemorySize, LG_SMEM);
    k_logits_f2<<<V_ / 256, 256, LG_SMEM>>>(h_new, W_out, b_out, logits);
}

// round 6
// speedup vs baseline: 1.6939x; 1.6939x over previous
#include <cuda_runtime.h>
#include <cuda_fp16.h>
#include <math.h>
#include <stdint.h>

// Problem dims
#define V_ 32000
#define E_ 1024
#define H_ 1024
#define A_ 10
#define S_ 512
#define B_ 64

#define NSPLIT 16

// Scratch layout (floats)
#define OFF_HWA1 0             // 640
#define OFF_E    1024          // S*B = 32768
#define OFF_XC   33792         // B*(E+H) = 131072
#define OFF_GIP  164864        // 4*B*3H = 786432
#define OFF_GHP  951296        // 4*B*3H = 786432
#define OFF_CP   1737728       // NSPLIT*B*H = 1048576
#define OFF_AH   2786304       // B*H fp16 = 32768 floats
#define SCRATCH_FLOATS 2819072

__device__ float g_scratch[SCRATCH_FLOATS];

// ---------------------------------------------------------------------------
// hWa1[b][a] = sum_h h_last[b,h] * Wa1[a,h]
// ---------------------------------------------------------------------------
__global__ __launch_bounds__(256) void k_hWa1(const float* __restrict__ h,
                                              const float* __restrict__ Wa1,
                                              float* __restrict__ hWa1)
{
    const int b = blockIdx.x;
    const int tid = threadIdx.x;
    float4 hv = ((const float4*)(h + (size_t)b * H_))[tid];
    float p[A_];
#pragma unroll
    for (int a = 0; a < A_; a++) {
        float4 w = ((const float4*)(Wa1 + (size_t)a * (2 * H_)))[tid];
        p[a] = hv.x * w.x + hv.y * w.y + hv.z * w.z + hv.w * w.w;
    }
    __shared__ float red[8][A_];
    const int lane = tid & 31, wid = tid >> 5;
#pragma unroll
    for (int a = 0; a < A_; a++) {
        float v = p[a];
        v += __shfl_xor_sync(0xffffffffu, v, 16);
        v += __shfl_xor_sync(0xffffffffu, v, 8);
        v += __shfl_xor_sync(0xffffffffu, v, 4);
        v += __shfl_xor_sync(0xffffffffu, v, 2);
        v += __shfl_xor_sync(0xffffffffu, v, 1);
        if (lane == 0) red[wid][a] = v;
    }
    __syncthreads();
    if (tid < A_) {
        float s = 0.f;
#pragma unroll
        for (int w = 0; w < 8; w++) s += red[w][tid];
        hWa1[b * A_ + tid] = s;
    }
}

// ---------------------------------------------------------------------------
// scores: e[r] = sum_a Wa2[a]*tanh(hWa1[b][a] + enc[r,:].Wa1[a,H:])
// ---------------------------------------------------------------------------
__global__ __launch_bounds__(256) void k_scores(const float* __restrict__ enc,
                                                const float* __restrict__ Wa1,
                                                const float* __restrict__ Wa2,
                                                const float* __restrict__ hWa1,
                                                float* __restrict__ e_out)
{
    __shared__ float Wsh[A_ * H_];   // 40KB
    const int tid = threadIdx.x;
    for (int id = tid; id < A_ * (H_ / 4); id += 256) {
        int a = id >> 8;
        int c4 = id & 255;
        ((float4*)Wsh)[a * 256 + c4] =
            *(const float4*)(Wa1 + (size_t)a * (2 * H_) + H_ + (c4 << 2));
    }
    __syncthreads();

    const int lane = tid & 31, wid = tid >> 5;
    const size_t r0 = (size_t)blockIdx.x * 32 + wid * 4;
    const float4* e4 = (const float4*)enc;

    float acc0[A_], acc1[A_], acc2[A_], acc3[A_];
#pragma unroll
    for (int a = 0; a < A_; a++) { acc0[a] = 0.f; acc1[a] = 0.f; acc2[a] = 0.f; acc3[a] = 0.f; }

#pragma unroll
    for (int it = 0; it < 8; it++) {
        const int h4 = it * 32 + lane;
        float4 x0 = e4[(r0 + 0) * 256 + h4];
        float4 x1 = e4[(r0 + 1) * 256 + h4];
        float4 x2 = e4[(r0 + 2) * 256 + h4];
        float4 x3 = e4[(r0 + 3) * 256 + h4];
#pragma unroll
        for (int a = 0; a < A_; a++) {
            float4 w = ((const float4*)Wsh)[a * 256 + h4];
            acc0[a] += x0.x * w.x + x0.y * w.y + x0.z * w.z + x0.w * w.w;
            acc1[a] += x1.x * w.x + x1.y * w.y + x1.z * w.z + x1.w * w.w;
            acc2[a] += x2.x * w.x + x2.y * w.y + x2.z * w.z + x2.w * w.w;
            acc3[a] += x3.x * w.x + x3.y * w.y + x3.z * w.z + x3.w * w.w;
        }
    }
#pragma unroll
    for (int a = 0; a < A_; a++) {
        float v;
        v = acc0[a];
        v += __shfl_xor_sync(0xffffffffu, v, 16); v += __shfl_xor_sync(0xffffffffu, v, 8);
        v += __shfl_xor_sync(0xffffffffu, v, 4);  v += __shfl_xor_sync(0xffffffffu, v, 2);
        v += __shfl_xor_sync(0xffffffffu, v, 1);  acc0[a] = v;
        v = acc1[a];
        v += __shfl_xor_sync(0xffffffffu, v, 16); v += __shfl_xor_sync(0xffffffffu, v, 8);
        v += __shfl_xor_sync(0xffffffffu, v, 4);  v += __shfl_xor_sync(0xffffffffu, v, 2);
        v += __shfl_xor_sync(0xffffffffu, v, 1);  acc1[a] = v;
        v = acc2[a];
        v += __shfl_xor_sync(0xffffffffu, v, 16); v += __shfl_xor_sync(0xffffffffu, v, 8);
        v += __shfl_xor_sync(0xffffffffu, v, 4);  v += __shfl_xor_sync(0xffffffffu, v, 2);
        v += __shfl_xor_sync(0xffffffffu, v, 1);  acc2[a] = v;
        v = acc3[a];
        v += __shfl_xor_sync(0xffffffffu, v, 16); v += __shfl_xor_sync(0xffffffffu, v, 8);
        v += __shfl_xor_sync(0xffffffffu, v, 4);  v += __shfl_xor_sync(0xffffffffu, v, 2);
        v += __shfl_xor_sync(0xffffffffu, v, 1);  acc3[a] = v;
    }
    float tsum[A_];
#pragma unroll
    for (int a = 0; a < A_; a++) {
        float t = acc0[a];
        if (lane == 1) t = acc1[a];
        if (lane == 2) t = acc2[a];
        if (lane == 3) t = acc3[a];
        tsum[a] = t;
    }
    if (lane < 4) {
        const size_t r = r0 + lane;
        const int b = (int)(r & (B_ - 1));
        float ev = 0.f;
#pragma unroll
        for (int a = 0; a < A_; a++)
            ev += Wa2[a] * tanhf(hWa1[b * A_ + a] + tsum[a]);
        e_out[r] = ev;
    }
}

// ---------------------------------------------------------------------------
// softmax over s (axis 0) per b, in place
// ---------------------------------------------------------------------------
__global__ __launch_bounds__(256) void k_softmax(float* __restrict__ e)
{
    const int b = blockIdx.x, tid = threadIdx.x;
    __shared__ float red[256];
    float v0 = e[(size_t)tid * B_ + b];
    float v1 = e[(size_t)(tid + 256) * B_ + b];
    red[tid] = fmaxf(v0, v1);
    __syncthreads();
    for (int s = 128; s > 0; s >>= 1) {
        if (tid < s) red[tid] = fmaxf(red[tid], red[tid + s]);
        __syncthreads();
    }
    const float M = red[0];
    __syncthreads();
    float e0 = expf(v0 - M), e1 = expf(v1 - M);
    red[tid] = e0 + e1;
    __syncthreads();
    for (int s = 128; s > 0; s >>= 1) {
        if (tid < s) red[tid] += red[tid + s];
        __syncthreads();
    }
    const float inv = 1.f / red[0];
    e[(size_t)tid * B_ + b] = e0 * inv;
    e[(size_t)(tid + 256) * B_ + b] = e1 * inv;
}

// ---------------------------------------------------------------------------
// context partials
// ---------------------------------------------------------------------------
__global__ __launch_bounds__(128) void k_context_part(const float* __restrict__ alpha,
                                                      const float* __restrict__ enc,
                                                      float* __restrict__ cp)
{
    const int b = blockIdx.y;
    const int sp = blockIdx.z;
    const int h0 = blockIdx.x * 512 + threadIdx.x * 4;
    __shared__ float al[S_ / NSPLIT];
    if (threadIdx.x < S_ / NSPLIT)
        al[threadIdx.x] = alpha[(size_t)(sp * (S_ / NSPLIT) + threadIdx.x) * B_ + b];
    __syncthreads();
    float4 acc = make_float4(0.f, 0.f, 0.f, 0.f);
    const float* base = enc + (size_t)(sp * (S_ / NSPLIT)) * B_ * H_ + (size_t)b * H_ + h0;
#pragma unroll
    for (int s = 0; s < S_ / NSPLIT; s++) {
        float4 v = *(const float4*)(base + (size_t)s * (B_ * H_));
        float a = al[s];
        acc.x += a * v.x; acc.y += a * v.y; acc.z += a * v.z; acc.w += a * v.w;
    }
    *(float4*)(cp + ((size_t)sp * B_ + b) * H_ + h0) = acc;
}

// ---------------------------------------------------------------------------
// ctx reduce + xc build
// ---------------------------------------------------------------------------
__global__ __launch_bounds__(256) void k_ctx_xc(const int* __restrict__ tok,
                                                const float* __restrict__ emb,
                                                const float* __restrict__ cp,
                                                float* __restrict__ xc)
{
    const int b = blockIdx.x, t = threadIdx.x;
    const int tk = tok[b];
    float4* x4 = (float4*)(xc + (size_t)b * (E_ + H_));
    x4[t] = ((const float4*)(emb + (size_t)tk * E_))[t];
    float4 acc = make_float4(0.f, 0.f, 0.f, 0.f);
#pragma unroll
    for (int sp = 0; sp < NSPLIT; sp++) {
        float4 v = ((const float4*)(cp + ((size_t)sp * B_ + b) * H_))[t];
        acc.x += v.x; acc.y += v.y; acc.z += v.z; acc.w += v.w;
    }
    x4[256 + t] = acc;
}

// ---------------------------------------------------------------------------
// fp32 GEMM (gi & gh in one launch): z=0 -> gh, z=1 -> gi. K-split 4.
// ---------------------------------------------------------------------------
__global__ __launch_bounds__(128) void k_gru_gemms(const float* __restrict__ Ah_,
                                                   const float* __restrict__ Ai_,
                                                   const float* __restrict__ Whh,
                                                   const float* __restrict__ Wih,
                                                   float* __restrict__ ghp,
                                                   float* __restrict__ gip)
{
    const float* A;
    const float* W;
    float* C;
    int K, klen;
    if (blockIdx.z == 0) { A = Ah_; W = Whh; C = ghp; K = H_;      klen = 256; }
    else                 { A = Ai_; W = Wih; C = gip; K = E_ + H_; klen = 512; }

    __shared__ float As[32 * 66];
    __shared__ float Ws[32 * 66];
    const int tid = threadIdx.x;
    const int tx = tid & 15;
    const int ty = tid >> 4;
    const int n0 = blockIdx.x * 64;
    const int kbase = blockIdx.y * klen;
    const int aoff = ty * 8 + ((ty >= 4) ? 1 : 0);
    const int woff = tx * 4 + ((tx >= 8) ? 1 : 0);

    float acc[8][4];
#pragma unroll
    for (int i = 0; i < 8; i++)
#pragma unroll
        for (int j = 0; j < 4; j++) acc[i][j] = 0.f;

    for (int kc = 0; kc < klen; kc += 32) {
        __syncthreads();
#pragma unroll
        for (int p = 0; p < 4; p++) {
            const int id = tid + p * 128;
            const int row = id >> 3;
            const int c4 = (id & 7) << 2;
            const int roff = row + (row >> 5);
            float4 av = *(const float4*)(A + (size_t)row * K + kbase + kc + c4);
            As[(c4 + 0) * 66 + roff] = av.x;
            As[(c4 + 1) * 66 + roff] = av.y;
            As[(c4 + 2) * 66 + roff] = av.z;
            As[(c4 + 3) * 66 + roff] = av.w;
            float4 wv = *(const float4*)(W + (size_t)(n0 + row) * K + kbase + kc + c4);
            Ws[(c4 + 0) * 66 + roff] = wv.x;
            Ws[(c4 + 1) * 66 + roff] = wv.y;
            Ws[(c4 + 2) * 66 + roff] = wv.z;
            Ws[(c4 + 3) * 66 + roff] = wv.w;
        }
        __syncthreads();
#pragma unroll 8
        for (int kk = 0; kk < 32; kk++) {
            const float w0 = Ws[kk * 66 + woff + 0];
            const float w1 = Ws[kk * 66 + woff + 1];
            const float w2 = Ws[kk * 66 + woff + 2];
            const float w3 = Ws[kk * 66 + woff + 3];
#pragma unroll
            for (int i = 0; i < 8; i++) {
                const float a = As[kk * 66 + aoff + i];
                acc[i][0] += a * w0;
                acc[i][1] += a * w1;
                acc[i][2] += a * w2;
                acc[i][3] += a * w3;
            }
        }
    }
#pragma unroll
    for (int i = 0; i < 8; i++) {
        const size_t brow = (size_t)(blockIdx.y * 64 + ty * 8 + i);
        *(float4*)(C + brow * (3 * H_) + n0 + tx * 4) =
            make_float4(acc[i][0], acc[i][1], acc[i][2], acc[i][3]);
    }
}

// ---------------------------------------------------------------------------
// gates: merge partials, GRU nonlinearity, write h_new (f32) and fp16 copy
// ---------------------------------------------------------------------------
__global__ __launch_bounds__(256) void k_gates(const float* __restrict__ gip,
                                               const float* __restrict__ ghp,
                                               const float* __restrict__ b_ih,
                                               const float* __restrict__ b_hh,
                                               const float* __restrict__ h_last,
                                               float* __restrict__ h_new,
                                               __half* __restrict__ h_half)
{
    const int idx = blockIdx.x * blockDim.x + threadIdx.x;
    const int b = idx >> 10;
    const int h = idx & 1023;
    float ir = 0.f, iz = 0.f, in_ = 0.f;
#pragma unroll
    for (int sp = 0; sp < 4; sp++) {
        const float* g = gip + (size_t)(sp * B_ + b) * (3 * H_);
        ir += g[h];
        iz += g[h + H_];
        in_ += g[h + 2 * H_];
    }
    float hr = 0.f, hz = 0.f, hn = 0.f;
#pragma unroll
    for (int sp = 0; sp < 4; sp++) {
        const float* g = ghp + (size_t)(sp * B_ + b) * (3 * H_);
        hr += g[h];
        hz += g[h + H_];
        hn += g[h + 2 * H_];
    }
    ir += b_ih[h];           hr += b_hh[h];
    iz += b_ih[h + H_];      hz += b_hh[h + H_];
    in_ += b_ih[h + 2 * H_]; hn += b_hh[h + 2 * H_];
    const float r = 1.f / (1.f + expf(-(ir + hr)));
    const float z = 1.f / (1.f + expf(-(iz + hz)));
    const float n = tanhf(in_ + r * hn);
    const float hv = (1.f - z) * n + z * h_last[idx];
    h_new[idx] = hv;
    h_half[idx] = __float2half_rn(hv);
}

// ---------------------------------------------------------------------------
// logits GEMM via fp16 mma.sync (single term).
// C[64,32000] = A[64,1024].W[32000,1024]^T + bias
// grid(250), block(256)=8 warps. N-tile 128 (warp n16), M=64, k-chunk 32.
// W converted f32->fp16 in-kernel; A pre-converted (k_gates).
// ---------------------------------------------------------------------------
#define SSTR 40   // smem row stride in halves (80B)

#define MMA_F16(d, a0, a1, a2, a3, b0, b1)                                    \
    asm volatile("mma.sync.aligned.m16n8k16.row.col.f32.f16.f16.f32 "         \
                 "{%0,%1,%2,%3}, {%4,%5,%6,%7}, {%8,%9}, {%0,%1,%2,%3};"      \
                 : "+f"(d[0]), "+f"(d[1]), "+f"(d[2]), "+f"(d[3])             \
                 : "r"(a0), "r"(a1), "r"(a2), "r"(a3), "r"(b0), "r"(b1))

__global__ __launch_bounds__(256) void k_logits_h(const __half* __restrict__ Ahalf,
                                                  const float* __restrict__ W,
                                                  const float* __restrict__ bias,
                                                  float* __restrict__ C)
{
    __shared__ __align__(16) __half Wh[128][SSTR];
    __shared__ __align__(16) __half Ash[64][SSTR];

    const int tid = threadIdx.x;
    const int wid = tid >> 5, lane = tid & 31;
    const int g = lane >> 2, tg = lane & 3;
    const int n0 = blockIdx.x * 128;

    // W loader: warp wid covers rows [wid*16, wid*16+16); per q-step 4 rows,
    // lane -> row wid*16 + q*4 + (lane>>3), 16B chunk (lane&7) of the row's 128B.
    const int wr_sub = lane >> 3;       // 0..3
    const int wr_col = (lane & 7) * 4;  // float col within 32-float chunk

    // A loader: 64 rows x 64B per chunk; thread -> row tid>>2, 16B piece tid&3.
    const int ar = tid >> 2;
    const int ac = (tid & 3) * 8;       // halves

    float acc[4][2][4];
#pragma unroll
    for (int mt = 0; mt < 4; mt++)
#pragma unroll
        for (int nt = 0; nt < 2; nt++)
#pragma unroll
            for (int q = 0; q < 4; q++) acc[mt][nt][q] = 0.f;

    // prefetch chunk 0
    float4 wreg[4];
    uint4 areg;
#pragma unroll
    for (int q = 0; q < 4; q++)
        wreg[q] = *(const float4*)(W + (size_t)(n0 + wid * 16 + q * 4 + wr_sub) * 1024 + wr_col);
    areg = *(const uint4*)((const uint8_t*)Ahalf + (size_t)ar * 2048 + ac * 2);

    for (int ch = 0; ch < 32; ch++) {
        __syncthreads();   // previous chunk consumed
        // cvt + STS W (uint2 = 4 halves)
#pragma unroll
        for (int q = 0; q < 4; q++) {
            __half2 p0 = __floats2half2_rn(wreg[q].x, wreg[q].y);
            __half2 p1 = __floats2half2_rn(wreg[q].z, wreg[q].w);
            uint2 pk;
            pk.x = *reinterpret_cast<uint32_t*>(&p0);
            pk.y = *reinterpret_cast<uint32_t*>(&p1);
            *(uint2*)&Wh[wid * 16 + q * 4 + wr_sub][wr_col] = pk;
        }
        *(uint4*)&Ash[ar][ac] = areg;
        __syncthreads();   // chunk visible
        // prefetch next chunk
        if (ch < 31) {
            const int kf = (ch + 1) * 32;
#pragma unroll
            for (int q = 0; q < 4; q++)
                wreg[q] = *(const float4*)(W + (size_t)(n0 + wid * 16 + q * 4 + wr_sub) * 1024 + kf + wr_col);
            areg = *(const uint4*)((const uint8_t*)Ahalf + (size_t)ar * 2048 + (kf + (tid & 3) * 8) * 2);
        }
        // compute: 2 k16 steps x 4 mt x 2 nt
#pragma unroll
        for (int ks = 0; ks < 2; ks++) {
            const int k0 = ks * 16;
            uint32_t bf[2][2];
#pragma unroll
            for (int nt = 0; nt < 2; nt++) {
                const int r = wid * 16 + nt * 8 + g;
                bf[nt][0] = *(const uint32_t*)&Wh[r][k0 + 2 * tg];
                bf[nt][1] = *(const uint32_t*)&Wh[r][k0 + 2 * tg + 8];
            }
#pragma unroll
            for (int mt = 0; mt < 4; mt++) {
                const int r0 = mt * 16 + g;
                uint32_t a0 = *(const uint32_t*)&Ash[r0][k0 + 2 * tg];
                uint32_t a1 = *(const uint32_t*)&Ash[r0 + 8][k0 + 2 * tg];
                uint32_t a2 = *(const uint32_t*)&Ash[r0][k0 + 2 * tg + 8];
                uint32_t a3 = *(const uint32_t*)&Ash[r0 + 8][k0 + 2 * tg + 8];
                MMA_F16(acc[mt][0], a0, a1, a2, a3, bf[0][0], bf[0][1]);
                MMA_F16(acc[mt][1], a0, a1, a2, a3, bf[1][0], bf[1][1]);
            }
        }
    }
    // epilogue: bias + store
#pragma unroll
    for (int mt = 0; mt < 4; mt++) {
        const int r0 = mt * 16 + g;
#pragma unroll
        for (int nt = 0; nt < 2; nt++) {
            const int col = n0 + wid * 16 + nt * 8 + 2 * tg;
            float2 bb = *(const float2*)(bias + col);
            *(float2*)(C + (size_t)r0 * V_ + col) =
                make_float2(acc[mt][nt][0] + bb.x, acc[mt][nt][1] + bb.y);
            *(float2*)(C + (size_t)(r0 + 8) * V_ + col) =
                make_float2(acc[mt][nt][2] + bb.x, acc[mt][nt][3] + bb.y);
        }
    }
}

// ---------------------------------------------------------------------------
extern "C" void kernel_launch(void* const* d_in, const int* in_sizes, int n_in,
                              void* d_out, int out_size)
{
    (void)in_sizes; (void)n_in; (void)out_size;
    const int* dec_input = (const int*)d_in[0];
    const float* dec_hidden = (const float*)d_in[1];
    const float* enc = (const float*)d_in[2];
    const float* emb = (const float*)d_in[3];
    const float* Wa1 = (const float*)d_in[4];
    const float* Wa2 = (const float*)d_in[5];
    const float* W_ih = (const float*)d_in[6];
    const float* W_hh = (const float*)d_in[7];
    const float* b_ih = (const float*)d_in[8];
    const float* b_hh = (const float*)d_in[9];
    const float* W_out = (const float*)d_in[10];
    const float* b_out = (const float*)d_in[11];

    float* out = (float*)d_out;
    float* logits = out;
    float* h_new = out + (size_t)B_ * V_;

    float* scratch = nullptr;
    cudaGetSymbolAddress((void**)&scratch, g_scratch);
    float* hWa1 = scratch + OFF_HWA1;
    float* e = scratch + OFF_E;
    float* xc = scratch + OFF_XC;
    float* gip = scratch + OFF_GIP;
    float* ghp = scratch + OFF_GHP;
    float* cp = scratch + OFF_CP;
    __half* Ahalf = (__half*)(scratch + OFF_AH);

    // attention
    k_hWa1<<<B_, 256>>>(dec_hidden, Wa1, hWa1);
    k_scores<<<(S_ * B_) / 32, 256>>>(enc, Wa1, Wa2, hWa1, e);
    k_softmax<<<B_, 256>>>(e);
    k_context_part<<<dim3(2, B_, NSPLIT), 128>>>(e, enc, cp);
    k_ctx_xc<<<B_, 256>>>(dec_input, emb, cp, xc);

    // GRU
    k_gru_gemms<<<dim3(48, 4, 2), 128>>>(dec_hidden, xc, W_hh, W_ih, ghp, gip);
    k_gates<<<(B_ * H_) / 256, 256>>>(gip, ghp, b_ih, b_hh, dec_hidden, h_new, Ahalf);

    // logits (single-term fp16 mma)
    k_logits_h<<<V_ / 128, 256>>>(Ahalf, W_out, b_out, logits);
}

// round 7
// speedup vs baseline: 1.9705x; 1.1633x over previous
#include <cuda_runtime.h>
#include <cuda_fp16.h>
#include <math.h>
#include <stdint.h>

// Problem dims
#define V_ 32000
#define E_ 1024
#define H_ 1024
#define A_ 10
#define S_ 512
#define B_ 64

#define NSPLIT 16

// Scratch layout (floats)
#define OFF_HWA1 0             // 640
#define OFF_E    1024          // S*B = 32768
#define OFF_XCH  33792         // 64*2048 fp16 = 65536 floats
#define OFF_HLH  99328         // 64*1024 fp16 = 32768 floats
#define OFF_GIP  132096        // 4*B*3H = 786432
#define OFF_GHP  918528        // 2*B*3H = 393216
#define OFF_CP   1311744       // NSPLIT*B*H = 1048576
#define OFF_AH   2360320       // B*H fp16 = 32768 floats
#define SCRATCH_FLOATS 2393088

__device__ float g_scratch[SCRATCH_FLOATS];

// ---------------------------------------------------------------------------
// hWa1[b][a] = sum_h h_last[b,h]*Wa1[a,h]; also emit h_last as fp16
// ---------------------------------------------------------------------------
__global__ __launch_bounds__(256) void k_hWa1(const float* __restrict__ h,
                                              const float* __restrict__ Wa1,
                                              float* __restrict__ hWa1,
                                              __half* __restrict__ hlh)
{
    const int b = blockIdx.x;
    const int tid = threadIdx.x;
    float4 hv = ((const float4*)(h + (size_t)b * H_))[tid];
    {
        __half2 p0 = __floats2half2_rn(hv.x, hv.y);
        __half2 p1 = __floats2half2_rn(hv.z, hv.w);
        uint2 pk;
        pk.x = *reinterpret_cast<uint32_t*>(&p0);
        pk.y = *reinterpret_cast<uint32_t*>(&p1);
        *(uint2*)(hlh + (size_t)b * H_ + 4 * tid) = pk;
    }
    float p[A_];
#pragma unroll
    for (int a = 0; a < A_; a++) {
        float4 w = ((const float4*)(Wa1 + (size_t)a * (2 * H_)))[tid];
        p[a] = hv.x * w.x + hv.y * w.y + hv.z * w.z + hv.w * w.w;
    }
    __shared__ float red[8][A_];
    const int lane = tid & 31, wid = tid >> 5;
#pragma unroll
    for (int a = 0; a < A_; a++) {
        float v = p[a];
        v += __shfl_xor_sync(0xffffffffu, v, 16);
        v += __shfl_xor_sync(0xffffffffu, v, 8);
        v += __shfl_xor_sync(0xffffffffu, v, 4);
        v += __shfl_xor_sync(0xffffffffu, v, 2);
        v += __shfl_xor_sync(0xffffffffu, v, 1);
        if (lane == 0) red[wid][a] = v;
    }
    __syncthreads();
    if (tid < A_) {
        float s = 0.f;
#pragma unroll
        for (int w = 0; w < 8; w++) s += red[w][tid];
        hWa1[b * A_ + tid] = s;
    }
}

// ---------------------------------------------------------------------------
// scores
// ---------------------------------------------------------------------------
__global__ __launch_bounds__(256) void k_scores(const float* __restrict__ enc,
                                                const float* __restrict__ Wa1,
                                                const float* __restrict__ Wa2,
                                                const float* __restrict__ hWa1,
                                                float* __restrict__ e_out)
{
    __shared__ float Wsh[A_ * H_];
    const int tid = threadIdx.x;
    for (int id = tid; id < A_ * (H_ / 4); id += 256) {
        int a = id >> 8;
        int c4 = id & 255;
        ((float4*)Wsh)[a * 256 + c4] =
            *(const float4*)(Wa1 + (size_t)a * (2 * H_) + H_ + (c4 << 2));
    }
    __syncthreads();

    const int lane = tid & 31, wid = tid >> 5;
    const size_t r0 = (size_t)blockIdx.x * 32 + wid * 4;
    const float4* e4 = (const float4*)enc;

    float acc0[A_], acc1[A_], acc2[A_], acc3[A_];
#pragma unroll
    for (int a = 0; a < A_; a++) { acc0[a] = 0.f; acc1[a] = 0.f; acc2[a] = 0.f; acc3[a] = 0.f; }

#pragma unroll
    for (int it = 0; it < 8; it++) {
        const int h4 = it * 32 + lane;
        float4 x0 = e4[(r0 + 0) * 256 + h4];
        float4 x1 = e4[(r0 + 1) * 256 + h4];
        float4 x2 = e4[(r0 + 2) * 256 + h4];
        float4 x3 = e4[(r0 + 3) * 256 + h4];
#pragma unroll
        for (int a = 0; a < A_; a++) {
            float4 w = ((const float4*)Wsh)[a * 256 + h4];
            acc0[a] += x0.x * w.x + x0.y * w.y + x0.z * w.z + x0.w * w.w;
            acc1[a] += x1.x * w.x + x1.y * w.y + x1.z * w.z + x1.w * w.w;
            acc2[a] += x2.x * w.x + x2.y * w.y + x2.z * w.z + x2.w * w.w;
            acc3[a] += x3.x * w.x + x3.y * w.y + x3.z * w.z + x3.w * w.w;
        }
    }
#pragma unroll
    for (int a = 0; a < A_; a++) {
        float v;
        v = acc0[a];
        v += __shfl_xor_sync(0xffffffffu, v, 16); v += __shfl_xor_sync(0xffffffffu, v, 8);
        v += __shfl_xor_sync(0xffffffffu, v, 4);  v += __shfl_xor_sync(0xffffffffu, v, 2);
        v += __shfl_xor_sync(0xffffffffu, v, 1);  acc0[a] = v;
        v = acc1[a];
        v += __shfl_xor_sync(0xffffffffu, v, 16); v += __shfl_xor_sync(0xffffffffu, v, 8);
        v += __shfl_xor_sync(0xffffffffu, v, 4);  v += __shfl_xor_sync(0xffffffffu, v, 2);
        v += __shfl_xor_sync(0xffffffffu, v, 1);  acc1[a] = v;
        v = acc2[a];
        v += __shfl_xor_sync(0xffffffffu, v, 16); v += __shfl_xor_sync(0xffffffffu, v, 8);
        v += __shfl_xor_sync(0xffffffffu, v, 4);  v += __shfl_xor_sync(0xffffffffu, v, 2);
        v += __shfl_xor_sync(0xffffffffu, v, 1);  acc2[a] = v;
        v = acc3[a];
        v += __shfl_xor_sync(0xffffffffu, v, 16); v += __shfl_xor_sync(0xffffffffu, v, 8);
        v += __shfl_xor_sync(0xffffffffu, v, 4);  v += __shfl_xor_sync(0xffffffffu, v, 2);
        v += __shfl_xor_sync(0xffffffffu, v, 1);  acc3[a] = v;
    }
    float tsum[A_];
#pragma unroll
    for (int a = 0; a < A_; a++) {
        float t = acc0[a];
        if (lane == 1) t = acc1[a];
        if (lane == 2) t = acc2[a];
        if (lane == 3) t = acc3[a];
        tsum[a] = t;
    }
    if (lane < 4) {
        const size_t r = r0 + lane;
        const int b = (int)(r & (B_ - 1));
        float ev = 0.f;
#pragma unroll
        for (int a = 0; a < A_; a++)
            ev += Wa2[a] * tanhf(hWa1[b * A_ + a] + tsum[a]);
        e_out[r] = ev;
    }
}

// ---------------------------------------------------------------------------
// softmax over s (axis 0) per b, in place
// ---------------------------------------------------------------------------
__global__ __launch_bounds__(256) void k_softmax(float* __restrict__ e)
{
    const int b = blockIdx.x, tid = threadIdx.x;
    __shared__ float red[256];
    float v0 = e[(size_t)tid * B_ + b];
    float v1 = e[(size_t)(tid + 256) * B_ + b];
    red[tid] = fmaxf(v0, v1);
    __syncthreads();
    for (int s = 128; s > 0; s >>= 1) {
        if (tid < s) red[tid] = fmaxf(red[tid], red[tid + s]);
        __syncthreads();
    }
    const float M = red[0];
    __syncthreads();
    float e0 = expf(v0 - M), e1 = expf(v1 - M);
    red[tid] = e0 + e1;
    __syncthreads();
    for (int s = 128; s > 0; s >>= 1) {
        if (tid < s) red[tid] += red[tid + s];
        __syncthreads();
    }
    const float inv = 1.f / red[0];
    e[(size_t)tid * B_ + b] = e0 * inv;
    e[(size_t)(tid + 256) * B_ + b] = e1 * inv;
}

// ---------------------------------------------------------------------------
// context partials
// ---------------------------------------------------------------------------
__global__ __launch_bounds__(128) void k_context_part(const float* __restrict__ alpha,
                                                      const float* __restrict__ enc,
                                                      float* __restrict__ cp)
{
    const int b = blockIdx.y;
    const int sp = blockIdx.z;
    const int h0 = blockIdx.x * 512 + threadIdx.x * 4;
    __shared__ float al[S_ / NSPLIT];
    if (threadIdx.x < S_ / NSPLIT)
        al[threadIdx.x] = alpha[(size_t)(sp * (S_ / NSPLIT) + threadIdx.x) * B_ + b];
    __syncthreads();
    float4 acc = make_float4(0.f, 0.f, 0.f, 0.f);
    const float* base = enc + (size_t)(sp * (S_ / NSPLIT)) * B_ * H_ + (size_t)b * H_ + h0;
#pragma unroll
    for (int s = 0; s < S_ / NSPLIT; s++) {
        float4 v = *(const float4*)(base + (size_t)s * (B_ * H_));
        float a = al[s];
        acc.x += a * v.x; acc.y += a * v.y; acc.z += a * v.z; acc.w += a * v.w;
    }
    *(float4*)(cp + ((size_t)sp * B_ + b) * H_ + h0) = acc;
}

// ---------------------------------------------------------------------------
// ctx reduce + xc build (fp16 output): xch[b] = fp16([emb[tok[b]]; c[b]])
// ---------------------------------------------------------------------------
__global__ __launch_bounds__(256) void k_ctx_xc(const int* __restrict__ tok,
                                                const float* __restrict__ emb,
                                                const float* __restrict__ cp,
                                                __half* __restrict__ xch)
{
    const int b = blockIdx.x, t = threadIdx.x;
    const int tk = tok[b];
    float4 ev = ((const float4*)(emb + (size_t)tk * E_))[t];
    {
        __half2 p0 = __floats2half2_rn(ev.x, ev.y);
        __half2 p1 = __floats2half2_rn(ev.z, ev.w);
        uint2 pk;
        pk.x = *reinterpret_cast<uint32_t*>(&p0);
        pk.y = *reinterpret_cast<uint32_t*>(&p1);
        *(uint2*)(xch + (size_t)b * (E_ + H_) + 4 * t) = pk;
    }
    float4 acc = make_float4(0.f, 0.f, 0.f, 0.f);
#pragma unroll
    for (int sp = 0; sp < NSPLIT; sp++) {
        float4 v = ((const float4*)(cp + ((size_t)sp * B_ + b) * H_))[t];
        acc.x += v.x; acc.y += v.y; acc.z += v.z; acc.w += v.w;
    }
    {
        __half2 p0 = __floats2half2_rn(acc.x, acc.y);
        __half2 p1 = __floats2half2_rn(acc.z, acc.w);
        uint2 pk;
        pk.x = *reinterpret_cast<uint32_t*>(&p0);
        pk.y = *reinterpret_cast<uint32_t*>(&p1);
        *(uint2*)(xch + (size_t)b * (E_ + H_) + E_ + 4 * t) = pk;
    }
}

// ---------------------------------------------------------------------------
// fp16 HMMA GEMM body: C[64, n0..n0+128) (+=bias) = A[64,K-range].W^T
// block(128) = 4 warps; warp tile m64 x n32; k-chunk 32; double-buffered smem.
// W fp32 in gmem (converted in-kernel), A fp16 in gmem.
// ---------------------------------------------------------------------------
#define SSTR 40   // smem row stride in halves (80B)

#define MMA_F16(d, a0, a1, a2, a3, b0, b1)                                    \
    asm volatile("mma.sync.aligned.m16n8k16.row.col.f32.f16.f16.f32 "         \
                 "{%0,%1,%2,%3}, {%4,%5,%6,%7}, {%8,%9}, {%0,%1,%2,%3};"      \
                 : "+f"(d[0]), "+f"(d[1]), "+f"(d[2]), "+f"(d[3])             \
                 : "r"(a0), "r"(a1), "r"(a2), "r"(a3), "r"(b0), "r"(b1))

__device__ __forceinline__ void gemm_h16_body(
    const __half* __restrict__ A, int lda,
    const float* __restrict__ W,
    const float* __restrict__ bias,
    float* __restrict__ C, size_t ldc,
    int n0, int kbase, int klen)
{
    __shared__ __align__(16) __half Wh[2][128][SSTR];
    __shared__ __align__(16) __half Ash[2][64][SSTR];

    const int tid = threadIdx.x;
    const int wid = tid >> 5, lane = tid & 31;
    const int g = lane >> 2, tg = lane & 3;

    const float* wg = W + (size_t)(n0 + tid) * lda + kbase;
    const int ar = tid >> 1;
    const int ac = (tid & 1) * 16;             // halves within 32-half chunk
    const __half* ag = A + (size_t)ar * lda + kbase + ac;

    float acc[4][4][4];
#pragma unroll
    for (int mt = 0; mt < 4; mt++)
#pragma unroll
        for (int nt = 0; nt < 4; nt++)
#pragma unroll
            for (int q = 0; q < 4; q++) acc[mt][nt][q] = 0.f;

    const int nch = klen >> 5;

    // prefetch chunk 0
    float4 wreg[8];
    uint4 areg[2];
#pragma unroll
    for (int q = 0; q < 8; q++) wreg[q] = *(const float4*)(wg + q * 4);
    areg[0] = ((const uint4*)ag)[0];
    areg[1] = ((const uint4*)ag)[1];

    for (int ch = 0; ch < nch; ch++) {
        const int buf = ch & 1;
        // STS current regs
#pragma unroll
        for (int q = 0; q < 8; q += 2) {
            __half2 p0 = __floats2half2_rn(wreg[q].x, wreg[q].y);
            __half2 p1 = __floats2half2_rn(wreg[q].z, wreg[q].w);
            __half2 p2 = __floats2half2_rn(wreg[q + 1].x, wreg[q + 1].y);
            __half2 p3 = __floats2half2_rn(wreg[q + 1].z, wreg[q + 1].w);
            uint4 pk;
            pk.x = *reinterpret_cast<uint32_t*>(&p0);
            pk.y = *reinterpret_cast<uint32_t*>(&p1);
            pk.z = *reinterpret_cast<uint32_t*>(&p2);
            pk.w = *reinterpret_cast<uint32_t*>(&p3);
            *(uint4*)&Wh[buf][tid][q * 4] = pk;
        }
        *(uint4*)&Ash[buf][ar][ac] = areg[0];
        *(uint4*)&Ash[buf][ar][ac + 8] = areg[1];
        __syncthreads();
        // prefetch next chunk
        if (ch + 1 < nch) {
            const float* wg2 = wg + (ch + 1) * 32;
#pragma unroll
            for (int q = 0; q < 8; q++) wreg[q] = *(const float4*)(wg2 + q * 4);
            const __half* ag2 = ag + (ch + 1) * 32;
            areg[0] = ((const uint4*)ag2)[0];
            areg[1] = ((const uint4*)ag2)[1];
        }
        // compute 2 x k16
#pragma unroll
        for (int ks = 0; ks < 2; ks++) {
            const int k0 = ks * 16;
            uint32_t bf0[4], bf1[4];
#pragma unroll
            for (int nt = 0; nt < 4; nt++) {
                const int r = wid * 32 + nt * 8 + g;
                bf0[nt] = *(const uint32_t*)&Wh[buf][r][k0 + 2 * tg];
                bf1[nt] = *(const uint32_t*)&Wh[buf][r][k0 + 2 * tg + 8];
            }
#pragma unroll
            for (int mt = 0; mt < 4; mt++) {
                const int r0 = mt * 16 + g;
                uint32_t a0 = *(const uint32_t*)&Ash[buf][r0][k0 + 2 * tg];
                uint32_t a1 = *(const uint32_t*)&Ash[buf][r0 + 8][k0 + 2 * tg];
                uint32_t a2 = *(const uint32_t*)&Ash[buf][r0][k0 + 2 * tg + 8];
                uint32_t a3 = *(const uint32_t*)&Ash[buf][r0 + 8][k0 + 2 * tg + 8];
#pragma unroll
                for (int nt = 0; nt < 4; nt++)
                    MMA_F16(acc[mt][nt], a0, a1, a2, a3, bf0[nt], bf1[nt]);
            }
        }
    }
    // epilogue
#pragma unroll
    for (int mt = 0; mt < 4; mt++) {
        const int r0 = mt * 16 + g;
#pragma unroll
        for (int nt = 0; nt < 4; nt++) {
            const int col = n0 + wid * 32 + nt * 8 + 2 * tg;
            float bx = 0.f, by = 0.f;
            if (bias) { float2 bb = *(const float2*)(bias + col); bx = bb.x; by = bb.y; }
            *(float2*)(C + (size_t)r0 * ldc + col) =
                make_float2(acc[mt][nt][0] + bx, acc[mt][nt][1] + by);
            *(float2*)(C + (size_t)(r0 + 8) * ldc + col) =
                make_float2(acc[mt][nt][2] + bx, acc[mt][nt][3] + by);
        }
    }
}

// ---------------------------------------------------------------------------
// GRU GEMMs via fp16 HMMA: grid(24, 6): y<4 -> gi split y; y>=4 -> gh split
// ---------------------------------------------------------------------------
__global__ __launch_bounds__(128) void k_gru_h(const __half* __restrict__ xch,
                                               const __half* __restrict__ hlh,
                                               const float* __restrict__ Wih,
                                               const float* __restrict__ Whh,
                                               float* __restrict__ gip,
                                               float* __restrict__ ghp)
{
    const int y = blockIdx.y;
    if (y < 4) {
        gemm_h16_body(xch, E_ + H_, Wih, nullptr,
                      gip + (size_t)y * (64 * 3 * H_), 3 * H_,
                      blockIdx.x * 128, y * 512, 512);
    } else {
        gemm_h16_body(hlh, H_, Whh, nullptr,
                      ghp + (size_t)(y - 4) * (64 * 3 * H_), 3 * H_,
                      blockIdx.x * 128, (y - 4) * 512, 512);
    }
}

// ---------------------------------------------------------------------------
// logits GEMM via fp16 HMMA: grid(250)
// ---------------------------------------------------------------------------
__global__ __launch_bounds__(128) void k_logits_h(const __half* __restrict__ Ahalf,
                                                  const float* __restrict__ W,
                                                  const float* __restrict__ bias,
                                                  float* __restrict__ C)
{
    gemm_h16_body(Ahalf, H_, W, bias, C, V_, blockIdx.x * 128, 0, H_);
}

// ---------------------------------------------------------------------------
// gates: merge partials (gi:4, gh:2), GRU nonlinearity, h_new f32 + fp16
// ---------------------------------------------------------------------------
__global__ __launch_bounds__(256) void k_gates(const float* __restrict__ gip,
                                               const float* __restrict__ ghp,
                                               const float* __restrict__ b_ih,
                                               const float* __restrict__ b_hh,
                                               const float* __restrict__ h_last,
                                               float* __restrict__ h_new,
                                               __half* __restrict__ h_half)
{
    const int idx = blockIdx.x * blockDim.x + threadIdx.x;
    const int b = idx >> 10;
    const int h = idx & 1023;
    float ir = 0.f, iz = 0.f, in_ = 0.f;
#pragma unroll
    for (int sp = 0; sp < 4; sp++) {
        const float* g = gip + (size_t)(sp * B_ + b) * (3 * H_);
        ir += g[h];
        iz += g[h + H_];
        in_ += g[h + 2 * H_];
    }
    float hr = 0.f, hz = 0.f, hn = 0.f;
#pragma unroll
    for (int sp = 0; sp < 2; sp++) {
        const float* g = ghp + (size_t)(sp * B_ + b) * (3 * H_);
        hr += g[h];
        hz += g[h + H_];
        hn += g[h + 2 * H_];
    }
    ir += b_ih[h];           hr += b_hh[h];
    iz += b_ih[h + H_];      hz += b_hh[h + H_];
    in_ += b_ih[h + 2 * H_]; hn += b_hh[h + 2 * H_];
    const float r = 1.f / (1.f + expf(-(ir + hr)));
    const float z = 1.f / (1.f + expf(-(iz + hz)));
    const float n = tanhf(in_ + r * hn);
    const float hv = (1.f - z) * n + z * h_last[idx];
    h_new[idx] = hv;
    h_half[idx] = __float2half_rn(hv);
}

// ---------------------------------------------------------------------------
extern "C" void kernel_launch(void* const* d_in, const int* in_sizes, int n_in,
                              void* d_out, int out_size)
{
    (void)in_sizes; (void)n_in; (void)out_size;
    const int* dec_input = (const int*)d_in[0];
    const float* dec_hidden = (const float*)d_in[1];
    const float* enc = (const float*)d_in[2];
    const float* emb = (const float*)d_in[3];
    const float* Wa1 = (const float*)d_in[4];
    const float* Wa2 = (const float*)d_in[5];
    const float* W_ih = (const float*)d_in[6];
    const float* W_hh = (const float*)d_in[7];
    const float* b_ih = (const float*)d_in[8];
    const float* b_hh = (const float*)d_in[9];
    const float* W_out = (const float*)d_in[10];
    const float* b_out = (const float*)d_in[11];

    float* out = (float*)d_out;
    float* logits = out;
    float* h_new = out + (size_t)B_ * V_;

    float* scratch = nullptr;
    cudaGetSymbolAddress((void**)&scratch, g_scratch);
    float* hWa1 = scratch + OFF_HWA1;
    float* e = scratch + OFF_E;
    __half* xch = (__half*)(scratch + OFF_XCH);
    __half* hlh = (__half*)(scratch + OFF_HLH);
    float* gip = scratch + OFF_GIP;
    float* ghp = scratch + OFF_GHP;
    float* cp = scratch + OFF_CP;
    __half* Ahalf = (__half*)(scratch + OFF_AH);

    // attention
    k_hWa1<<<B_, 256>>>(dec_hidden, Wa1, hWa1, hlh);
    k_scores<<<(S_ * B_) / 32, 256>>>(enc, Wa1, Wa2, hWa1, e);
    k_softmax<<<B_, 256>>>(e);
    k_context_part<<<dim3(2, B_, NSPLIT), 128>>>(e, enc, cp);
    k_ctx_xc<<<B_, 256>>>(dec_input, emb, cp, xch);

    // GRU (fp16 HMMA)
    k_gru_h<<<dim3(3 * H_ / 128, 6), 128>>>(xch, hlh, W_ih, W_hh, gip, ghp);
    k_gates<<<(B_ * H_) / 256, 256>>>(gip, ghp, b_ih, b_hh, dec_hidden, h_new, Ahalf);

    // logits (fp16 HMMA)
    k_logits_h<<<V_ / 128, 128>>>(Ahalf, W_out, b_out, logits);
}

// round 8
// speedup vs baseline: 2.2642x; 1.1490x over previous
#include <cuda_runtime.h>
#include <cuda_fp16.h>
#include <math.h>
#include <stdint.h>

// Problem dims
#define V_ 32000
#define E_ 1024
#define H_ 1024
#define A_ 10
#define S_ 512
#define B_ 64

#define NSPLIT 16

// Scratch layout (floats)
#define OFF_HWA1 0             // 640
#define OFF_E    1024          // S*B = 32768
#define OFF_XCH  33792         // 64*2048 fp16 = 65536 floats
#define OFF_HLH  99328         // 64*1024 fp16 = 32768 floats
#define OFF_GIP  132096        // 4*B*3H = 786432
#define OFF_GHP  918528        // 2*B*3H = 393216
#define OFF_CP   1311744       // NSPLIT*B*H = 1048576
#define OFF_AH   2360320       // B*H fp16 = 32768 floats
#define SCRATCH_FLOATS 2393088

__device__ float g_scratch[SCRATCH_FLOATS];

// ---------------------------------------------------------------------------
// hWa1[b][a] = sum_h h_last[b,h]*Wa1[a,h]; also emit h_last as fp16
// ---------------------------------------------------------------------------
__global__ __launch_bounds__(256) void k_hWa1(const float* __restrict__ h,
                                              const float* __restrict__ Wa1,
                                              float* __restrict__ hWa1,
                                              __half* __restrict__ hlh)
{
    const int b = blockIdx.x;
    const int tid = threadIdx.x;
    float4 hv = ((const float4*)(h + (size_t)b * H_))[tid];
    {
        __half2 p0 = __floats2half2_rn(hv.x, hv.y);
        __half2 p1 = __floats2half2_rn(hv.z, hv.w);
        uint2 pk;
        pk.x = *reinterpret_cast<uint32_t*>(&p0);
        pk.y = *reinterpret_cast<uint32_t*>(&p1);
        *(uint2*)(hlh + (size_t)b * H_ + 4 * tid) = pk;
    }
    float p[A_];
#pragma unroll
    for (int a = 0; a < A_; a++) {
        float4 w = ((const float4*)(Wa1 + (size_t)a * (2 * H_)))[tid];
        p[a] = hv.x * w.x + hv.y * w.y + hv.z * w.z + hv.w * w.w;
    }
    __shared__ float red[8][A_];
    const int lane = tid & 31, wid = tid >> 5;
#pragma unroll
    for (int a = 0; a < A_; a++) {
        float v = p[a];
        v += __shfl_xor_sync(0xffffffffu, v, 16);
        v += __shfl_xor_sync(0xffffffffu, v, 8);
        v += __shfl_xor_sync(0xffffffffu, v, 4);
        v += __shfl_xor_sync(0xffffffffu, v, 2);
        v += __shfl_xor_sync(0xffffffffu, v, 1);
        if (lane == 0) red[wid][a] = v;
    }
    __syncthreads();
    if (tid < A_) {
        float s = 0.f;
#pragma unroll
        for (int w = 0; w < 8; w++) s += red[w][tid];
        hWa1[b * A_ + tid] = s;
    }
}

// ---------------------------------------------------------------------------
// scores
// ---------------------------------------------------------------------------
__global__ __launch_bounds__(256) void k_scores(const float* __restrict__ enc,
                                                const float* __restrict__ Wa1,
                                                const float* __restrict__ Wa2,
                                                const float* __restrict__ hWa1,
                                                float* __restrict__ e_out)
{
    __shared__ float Wsh[A_ * H_];
    const int tid = threadIdx.x;
    for (int id = tid; id < A_ * (H_ / 4); id += 256) {
        int a = id >> 8;
        int c4 = id & 255;
        ((float4*)Wsh)[a * 256 + c4] =
            *(const float4*)(Wa1 + (size_t)a * (2 * H_) + H_ + (c4 << 2));
    }
    __syncthreads();

    const int lane = tid & 31, wid = tid >> 5;
    const size_t r0 = (size_t)blockIdx.x * 32 + wid * 4;
    const float4* e4 = (const float4*)enc;

    float acc0[A_], acc1[A_], acc2[A_], acc3[A_];
#pragma unroll
    for (int a = 0; a < A_; a++) { acc0[a] = 0.f; acc1[a] = 0.f; acc2[a] = 0.f; acc3[a] = 0.f; }

#pragma unroll
    for (int it = 0; it < 8; it++) {
        const int h4 = it * 32 + lane;
        float4 x0 = e4[(r0 + 0) * 256 + h4];
        float4 x1 = e4[(r0 + 1) * 256 + h4];
        float4 x2 = e4[(r0 + 2) * 256 + h4];
        float4 x3 = e4[(r0 + 3) * 256 + h4];
#pragma unroll
        for (int a = 0; a < A_; a++) {
            float4 w = ((const float4*)Wsh)[a * 256 + h4];
            acc0[a] += x0.x * w.x + x0.y * w.y + x0.z * w.z + x0.w * w.w;
            acc1[a] += x1.x * w.x + x1.y * w.y + x1.z * w.z + x1.w * w.w;
            acc2[a] += x2.x * w.x + x2.y * w.y + x2.z * w.z + x2.w * w.w;
            acc3[a] += x3.x * w.x + x3.y * w.y + x3.z * w.z + x3.w * w.w;
        }
    }
#pragma unroll
    for (int a = 0; a < A_; a++) {
        float v;
        v = acc0[a];
        v += __shfl_xor_sync(0xffffffffu, v, 16); v += __shfl_xor_sync(0xffffffffu, v, 8);
        v += __shfl_xor_sync(0xffffffffu, v, 4);  v += __shfl_xor_sync(0xffffffffu, v, 2);
        v += __shfl_xor_sync(0xffffffffu, v, 1);  acc0[a] = v;
        v = acc1[a];
        v += __shfl_xor_sync(0xffffffffu, v, 16); v += __shfl_xor_sync(0xffffffffu, v, 8);
        v += __shfl_xor_sync(0xffffffffu, v, 4);  v += __shfl_xor_sync(0xffffffffu, v, 2);
        v += __shfl_xor_sync(0xffffffffu, v, 1);  acc1[a] = v;
        v = acc2[a];
        v += __shfl_xor_sync(0xffffffffu, v, 16); v += __shfl_xor_sync(0xffffffffu, v, 8);
        v += __shfl_xor_sync(0xffffffffu, v, 4);  v += __shfl_xor_sync(0xffffffffu, v, 2);
        v += __shfl_xor_sync(0xffffffffu, v, 1);  acc2[a] = v;
        v = acc3[a];
        v += __shfl_xor_sync(0xffffffffu, v, 16); v += __shfl_xor_sync(0xffffffffu, v, 8);
        v += __shfl_xor_sync(0xffffffffu, v, 4);  v += __shfl_xor_sync(0xffffffffu, v, 2);
        v += __shfl_xor_sync(0xffffffffu, v, 1);  acc3[a] = v;
    }
    float tsum[A_];
#pragma unroll
    for (int a = 0; a < A_; a++) {
        float t = acc0[a];
        if (lane == 1) t = acc1[a];
        if (lane == 2) t = acc2[a];
        if (lane == 3) t = acc3[a];
        tsum[a] = t;
    }
    if (lane < 4) {
        const size_t r = r0 + lane;
        const int b = (int)(r & (B_ - 1));
        float ev = 0.f;
#pragma unroll
        for (int a = 0; a < A_; a++)
            ev += Wa2[a] * tanhf(hWa1[b * A_ + a] + tsum[a]);
        e_out[r] = ev;
    }
}

// ---------------------------------------------------------------------------
// softmax over s (axis 0) per b, in place
// ---------------------------------------------------------------------------
__global__ __launch_bounds__(256) void k_softmax(float* __restrict__ e)
{
    const int b = blockIdx.x, tid = threadIdx.x;
    __shared__ float red[256];
    float v0 = e[(size_t)tid * B_ + b];
    float v1 = e[(size_t)(tid + 256) * B_ + b];
    red[tid] = fmaxf(v0, v1);
    __syncthreads();
    for (int s = 128; s > 0; s >>= 1) {
        if (tid < s) red[tid] = fmaxf(red[tid], red[tid + s]);
        __syncthreads();
    }
    const float M = red[0];
    __syncthreads();
    float e0 = expf(v0 - M), e1 = expf(v1 - M);
    red[tid] = e0 + e1;
    __syncthreads();
    for (int s = 128; s > 0; s >>= 1) {
        if (tid < s) red[tid] += red[tid + s];
        __syncthreads();
    }
    const float inv = 1.f / red[0];
    e[(size_t)tid * B_ + b] = e0 * inv;
    e[(size_t)(tid + 256) * B_ + b] = e1 * inv;
}

// ---------------------------------------------------------------------------
// context partials
// ---------------------------------------------------------------------------
__global__ __launch_bounds__(128) void k_context_part(const float* __restrict__ alpha,
                                                      const float* __restrict__ enc,
                                                      float* __restrict__ cp)
{
    const int b = blockIdx.y;
    const int sp = blockIdx.z;
    const int h0 = blockIdx.x * 512 + threadIdx.x * 4;
    __shared__ float al[S_ / NSPLIT];
    if (threadIdx.x < S_ / NSPLIT)
        al[threadIdx.x] = alpha[(size_t)(sp * (S_ / NSPLIT) + threadIdx.x) * B_ + b];
    __syncthreads();
    float4 acc = make_float4(0.f, 0.f, 0.f, 0.f);
    const float* base = enc + (size_t)(sp * (S_ / NSPLIT)) * B_ * H_ + (size_t)b * H_ + h0;
#pragma unroll
    for (int s = 0; s < S_ / NSPLIT; s++) {
        float4 v = *(const float4*)(base + (size_t)s * (B_ * H_));
        float a = al[s];
        acc.x += a * v.x; acc.y += a * v.y; acc.z += a * v.z; acc.w += a * v.w;
    }
    *(float4*)(cp + ((size_t)sp * B_ + b) * H_ + h0) = acc;
}

// ---------------------------------------------------------------------------
// ctx reduce + xc build (fp16 output): xch[b] = fp16([emb[tok[b]]; c[b]])
// ---------------------------------------------------------------------------
__global__ __launch_bounds__(256) void k_ctx_xc(const int* __restrict__ tok,
                                                const float* __restrict__ emb,
                                                const float* __restrict__ cp,
                                                __half* __restrict__ xch)
{
    const int b = blockIdx.x, t = threadIdx.x;
    const int tk = tok[b];
    float4 ev = ((const float4*)(emb + (size_t)tk * E_))[t];
    {
        __half2 p0 = __floats2half2_rn(ev.x, ev.y);
        __half2 p1 = __floats2half2_rn(ev.z, ev.w);
        uint2 pk;
        pk.x = *reinterpret_cast<uint32_t*>(&p0);
        pk.y = *reinterpret_cast<uint32_t*>(&p1);
        *(uint2*)(xch + (size_t)b * (E_ + H_) + 4 * t) = pk;
    }
    float4 acc = make_float4(0.f, 0.f, 0.f, 0.f);
#pragma unroll
    for (int sp = 0; sp < NSPLIT; sp++) {
        float4 v = ((const float4*)(cp + ((size_t)sp * B_ + b) * H_))[t];
        acc.x += v.x; acc.y += v.y; acc.z += v.z; acc.w += v.w;
    }
    {
        __half2 p0 = __floats2half2_rn(acc.x, acc.y);
        __half2 p1 = __floats2half2_rn(acc.z, acc.w);
        uint2 pk;
        pk.x = *reinterpret_cast<uint32_t*>(&p0);
        pk.y = *reinterpret_cast<uint32_t*>(&p1);
        *(uint2*)(xch + (size_t)b * (E_ + H_) + E_ + 4 * t) = pk;
    }
}

// ---------------------------------------------------------------------------
// fp16 HMMA GEMM body: C[64, n0..n0+128) (+=bias) = A[64,K-range].W^T
// block(128) = 4 warps; warp tile m64 x n32; k-chunk 32; double-buffered smem.
// W fp32 in gmem (converted in-kernel), A fp16 in gmem.
// W loads COALESCED: 8 lanes cover one 128B row-chunk (4 lines per LDG).
// ---------------------------------------------------------------------------
#define SSTR 40   // smem row stride in halves (80B)

#define MMA_F16(d, a0, a1, a2, a3, b0, b1)                                    \
    asm volatile("mma.sync.aligned.m16n8k16.row.col.f32.f16.f16.f32 "         \
                 "{%0,%1,%2,%3}, {%4,%5,%6,%7}, {%8,%9}, {%0,%1,%2,%3};"      \
                 : "+f"(d[0]), "+f"(d[1]), "+f"(d[2]), "+f"(d[3])             \
                 : "r"(a0), "r"(a1), "r"(a2), "r"(a3), "r"(b0), "r"(b1))

__device__ __forceinline__ void gemm_h16_body(
    const __half* __restrict__ A, int lda,
    const float* __restrict__ W,
    const float* __restrict__ bias,
    float* __restrict__ C, size_t ldc,
    int n0, int kbase, int klen)
{
    __shared__ __align__(16) __half Wh[2][128][SSTR];
    __shared__ __align__(16) __half Ash[2][64][SSTR];

    const int tid = threadIdx.x;
    const int wid = tid >> 5, lane = tid & 31;
    const int g = lane >> 2, tg = lane & 3;

    // W loader: idx = p*128 + tid -> row = p*16 + (tid>>3), piece = tid&7.
    // 8 consecutive lanes read 8 consecutive float4 of one row (1 line).
    const int wr_base = tid >> 3;          // 0..15
    const int wr_piece = tid & 7;          // float4 index within 32-float chunk
    const float* wg = W + (size_t)(n0 + wr_base) * lda + kbase + wr_piece * 4;
    const size_t wstep = (size_t)16 * lda; // 16 rows per p

    const int ar = tid >> 1;
    const int ac = (tid & 1) * 16;         // halves within 32-half chunk
    const __half* ag = A + (size_t)ar * lda + kbase + ac;

    float acc[4][4][4];
#pragma unroll
    for (int mt = 0; mt < 4; mt++)
#pragma unroll
        for (int nt = 0; nt < 4; nt++)
#pragma unroll
            for (int q = 0; q < 4; q++) acc[mt][nt][q] = 0.f;

    const int nch = klen >> 5;

    // prefetch chunk 0
    float4 wreg[8];
    uint4 areg[2];
#pragma unroll
    for (int p = 0; p < 8; p++) wreg[p] = *(const float4*)(wg + p * wstep);
    areg[0] = ((const uint4*)ag)[0];
    areg[1] = ((const uint4*)ag)[1];

    for (int ch = 0; ch < nch; ch++) {
        const int buf = ch & 1;
        // STS current regs (cvt f32x4 -> f16x4, 8B per store)
#pragma unroll
        for (int p = 0; p < 8; p++) {
            __half2 p0 = __floats2half2_rn(wreg[p].x, wreg[p].y);
            __half2 p1 = __floats2half2_rn(wreg[p].z, wreg[p].w);
            uint2 pk;
            pk.x = *reinterpret_cast<uint32_t*>(&p0);
            pk.y = *reinterpret_cast<uint32_t*>(&p1);
            *(uint2*)&Wh[buf][p * 16 + wr_base][wr_piece * 4] = pk;
        }
        *(uint4*)&Ash[buf][ar][ac] = areg[0];
        *(uint4*)&Ash[buf][ar][ac + 8] = areg[1];
        __syncthreads();
        // prefetch next chunk (hidden under compute)
        if (ch + 1 < nch) {
            const float* wg2 = wg + (ch + 1) * 32;
#pragma unroll
            for (int p = 0; p < 8; p++) wreg[p] = *(const float4*)(wg2 + p * wstep);
            const __half* ag2 = ag + (ch + 1) * 32;
            areg[0] = ((const uint4*)ag2)[0];
            areg[1] = ((const uint4*)ag2)[1];
        }
        // compute 2 x k16
#pragma unroll
        for (int ks = 0; ks < 2; ks++) {
            const int k0 = ks * 16;
            uint32_t bf0[4], bf1[4];
#pragma unroll
            for (int nt = 0; nt < 4; nt++) {
                const int r = wid * 32 + nt * 8 + g;
                bf0[nt] = *(const uint32_t*)&Wh[buf][r][k0 + 2 * tg];
                bf1[nt] = *(const uint32_t*)&Wh[buf][r][k0 + 2 * tg + 8];
            }
#pragma unroll
            for (int mt = 0; mt < 4; mt++) {
                const int r0 = mt * 16 + g;
                uint32_t a0 = *(const uint32_t*)&Ash[buf][r0][k0 + 2 * tg];
                uint32_t a1 = *(const uint32_t*)&Ash[buf][r0 + 8][k0 + 2 * tg];
                uint32_t a2 = *(const uint32_t*)&Ash[buf][r0][k0 + 2 * tg + 8];
                uint32_t a3 = *(const uint32_t*)&Ash[buf][r0 + 8][k0 + 2 * tg + 8];
#pragma unroll
                for (int nt = 0; nt < 4; nt++)
                    MMA_F16(acc[mt][nt], a0, a1, a2, a3, bf0[nt], bf1[nt]);
            }
        }
    }
    // epilogue
#pragma unroll
    for (int mt = 0; mt < 4; mt++) {
        const int r0 = mt * 16 + g;
#pragma unroll
        for (int nt = 0; nt < 4; nt++) {
            const int col = n0 + wid * 32 + nt * 8 + 2 * tg;
            float bx = 0.f, by = 0.f;
            if (bias) { float2 bb = *(const float2*)(bias + col); bx = bb.x; by = bb.y; }
            *(float2*)(C + (size_t)r0 * ldc + col) =
                make_float2(acc[mt][nt][0] + bx, acc[mt][nt][1] + by);
            *(float2*)(C + (size_t)(r0 + 8) * ldc + col) =
                make_float2(acc[mt][nt][2] + bx, acc[mt][nt][3] + by);
        }
    }
}

// ---------------------------------------------------------------------------
// GRU GEMMs via fp16 HMMA: grid(24, 6): y<4 -> gi split y; y>=4 -> gh split
// ---------------------------------------------------------------------------
__global__ __launch_bounds__(128) void k_gru_h(const __half* __restrict__ xch,
                                               const __half* __restrict__ hlh,
                                               const float* __restrict__ Wih,
                                               const float* __restrict__ Whh,
                                               float* __restrict__ gip,
                                               float* __restrict__ ghp)
{
    const int y = blockIdx.y;
    if (y < 4) {
        gemm_h16_body(xch, E_ + H_, Wih, nullptr,
                      gip + (size_t)y * (64 * 3 * H_), 3 * H_,
                      blockIdx.x * 128, y * 512, 512);
    } else {
        gemm_h16_body(hlh, H_, Whh, nullptr,
                      ghp + (size_t)(y - 4) * (64 * 3 * H_), 3 * H_,
                      blockIdx.x * 128, (y - 4) * 512, 512);
    }
}

// ---------------------------------------------------------------------------
// logits GEMM via fp16 HMMA: grid(250)
// ---------------------------------------------------------------------------
__global__ __launch_bounds__(128) void k_logits_h(const __half* __restrict__ Ahalf,
                                                  const float* __restrict__ W,
                                                  const float* __restrict__ bias,
                                                  float* __restrict__ C)
{
    gemm_h16_body(Ahalf, H_, W, bias, C, V_, blockIdx.x * 128, 0, H_);
}

// ---------------------------------------------------------------------------
// gates: merge partials (gi:4, gh:2), GRU nonlinearity, h_new f32 + fp16
// ---------------------------------------------------------------------------
__global__ __launch_bounds__(256) void k_gates(const float* __restrict__ gip,
                                               const float* __restrict__ ghp,
                                               const float* __restrict__ b_ih,
                                               const float* __restrict__ b_hh,
                                               const float* __restrict__ h_last,
                                               float* __restrict__ h_new,
                                               __half* __restrict__ h_half)
{
    const int idx = blockIdx.x * blockDim.x + threadIdx.x;
    const int b = idx >> 10;
    const int h = idx & 1023;
    float ir = 0.f, iz = 0.f, in_ = 0.f;
#pragma unroll
    for (int sp = 0; sp < 4; sp++) {
        const float* g = gip + (size_t)(sp * B_ + b) * (3 * H_);
        ir += g[h];
        iz += g[h + H_];
        in_ += g[h + 2 * H_];
    }
    float hr = 0.f, hz = 0.f, hn = 0.f;
#pragma unroll
    for (int sp = 0; sp < 2; sp++) {
        const float* g = ghp + (size_t)(sp * B_ + b) * (3 * H_);
        hr += g[h];
        hz += g[h + H_];
        hn += g[h + 2 * H_];
    }
    ir += b_ih[h];           hr += b_hh[h];
    iz += b_ih[h + H_];      hz += b_hh[h + H_];
    in_ += b_ih[h + 2 * H_]; hn += b_hh[h + 2 * H_];
    const float r = 1.f / (1.f + expf(-(ir + hr)));
    const float z = 1.f / (1.f + expf(-(iz + hz)));
    const float n = tanhf(in_ + r * hn);
    const float hv = (1.f - z) * n + z * h_last[idx];
    h_new[idx] = hv;
    h_half[idx] = __float2half_rn(hv);
}

// ---------------------------------------------------------------------------
extern "C" void kernel_launch(void* const* d_in, const int* in_sizes, int n_in,
                              void* d_out, int out_size)
{
    (void)in_sizes; (void)n_in; (void)out_size;
    const int* dec_input = (const int*)d_in[0];
    const float* dec_hidden = (const float*)d_in[1];
    const float* enc = (const float*)d_in[2];
    const float* emb = (const float*)d_in[3];
    const float* Wa1 = (const float*)d_in[4];
    const float* Wa2 = (const float*)d_in[5];
    const float* W_ih = (const float*)d_in[6];
    const float* W_hh = (const float*)d_in[7];
    const float* b_ih = (const float*)d_in[8];
    const float* b_hh = (const float*)d_in[9];
    const float* W_out = (const float*)d_in[10];
    const float* b_out = (const float*)d_in[11];

    float* out = (float*)d_out;
    float* logits = out;
    float* h_new = out + (size_t)B_ * V_;

    float* scratch = nullptr;
    cudaGetSymbolAddress((void**)&scratch, g_scratch);
    float* hWa1 = scratch + OFF_HWA1;
    float* e = scratch + OFF_E;
    __half* xch = (__half*)(scratch + OFF_XCH);
    __half* hlh = (__half*)(scratch + OFF_HLH);
    float* gip = scratch + OFF_GIP;
    float* ghp = scratch + OFF_GHP;
    float* cp = scratch + OFF_CP;
    __half* Ahalf = (__half*)(scratch + OFF_AH);

    // attention
    k_hWa1<<<B_, 256>>>(dec_hidden, Wa1, hWa1, hlh);
    k_scores<<<(S_ * B_) / 32, 256>>>(enc, Wa1, Wa2, hWa1, e);
    k_softmax<<<B_, 256>>>(e);
    k_context_part<<<dim3(2, B_, NSPLIT), 128>>>(e, enc, cp);
    k_ctx_xc<<<B_, 256>>>(dec_input, emb, cp, xch);

    // GRU (fp16 HMMA)
    k_gru_h<<<dim3(3 * H_ / 128, 6), 128>>>(xch, hlh, W_ih, W_hh, gip, ghp);
    k_gates<<<(B_ * H_) / 256, 256>>>(gip, ghp, b_ih, b_hh, dec_hidden, h_new, Ahalf);

    // logits (fp16 HMMA)
    k_logits_h<<<V_ / 128, 128>>>(Ahalf, W_out, b_out, logits);
}